// round 1
// baseline (speedup 1.0000x reference)
#include <cuda_runtime.h>
#include <math.h>

#define BATCH   4
#define NTOK    2048
#define CDIM    768
#define HEADS   16
#define HD      48
#define MROWS   (BATCH*NTOK)          // 8192
#define SCALE   0.14433756729740643f  // 48^-0.5

// ---------------- scratch (device globals; no allocation allowed) ----------
__device__ float g_Q[(size_t)BATCH*HEADS*NTOK*HD];
__device__ float g_K[(size_t)BATCH*HEADS*NTOK*HD];
__device__ float g_V[(size_t)BATCH*HEADS*NTOK*HD];
__device__ float g_Y[(size_t)MROWS*CDIM];

// ---------------------------------------------------------------------------
// GEMM: acc[m][c] = sum_k X[m][k] * W[c][k]      (y = x @ W^T)
// mode 0/1/2 : write acc+bias scattered into g_Q/g_K/g_V laid out [B,H,N,D]
// mode 3     : X := g_Y; out[m][c] = acc + bias[c] + g_Y[m][c] + addsrc[m][c]
// BM=BN=128, BK=8, 256 threads, 8x8 per thread.
// ---------------------------------------------------------------------------
__global__ __launch_bounds__(256) void gemm_kernel(
    const float* __restrict__ X, const float* __restrict__ W,
    const float* __restrict__ bias, float* __restrict__ outp,
    const float* __restrict__ addsrc, int mode)
{
    __shared__ float As[8][128];
    __shared__ float Bs[8][128];

    const float* Xp = (mode == 3) ? g_Y : X;

    int tid = threadIdx.x;
    int m0 = blockIdx.y * 128;
    int n0 = blockIdx.x * 128;
    int lr = tid >> 1;          // 0..127
    int lk = (tid & 1) * 4;     // 0 or 4

    const float* xg = Xp + (size_t)(m0 + lr) * CDIM + lk;
    const float* wg = W  + (size_t)(n0 + lr) * CDIM + lk;

    int ty = tid >> 4, tx = tid & 15;

    float acc[8][8];
    #pragma unroll
    for (int i = 0; i < 8; i++)
        #pragma unroll
        for (int j = 0; j < 8; j++) acc[i][j] = 0.f;

    for (int kt = 0; kt < CDIM; kt += 8) {
        float4 xa = *(const float4*)(xg + kt);
        float4 wa = *(const float4*)(wg + kt);
        __syncthreads();
        As[lk+0][lr] = xa.x; As[lk+1][lr] = xa.y;
        As[lk+2][lr] = xa.z; As[lk+3][lr] = xa.w;
        Bs[lk+0][lr] = wa.x; Bs[lk+1][lr] = wa.y;
        Bs[lk+2][lr] = wa.z; Bs[lk+3][lr] = wa.w;
        __syncthreads();

        #pragma unroll
        for (int kk = 0; kk < 8; kk++) {
            float a[8], b[8];
            float4 t0 = *(const float4*)&As[kk][ty*8];
            float4 t1 = *(const float4*)&As[kk][ty*8 + 4];
            a[0]=t0.x; a[1]=t0.y; a[2]=t0.z; a[3]=t0.w;
            a[4]=t1.x; a[5]=t1.y; a[6]=t1.z; a[7]=t1.w;
            float4 u0 = *(const float4*)&Bs[kk][tx*8];
            float4 u1 = *(const float4*)&Bs[kk][tx*8 + 4];
            b[0]=u0.x; b[1]=u0.y; b[2]=u0.z; b[3]=u0.w;
            b[4]=u1.x; b[5]=u1.y; b[6]=u1.z; b[7]=u1.w;
            #pragma unroll
            for (int i = 0; i < 8; i++)
                #pragma unroll
                for (int j = 0; j < 8; j++)
                    acc[i][j] += a[i] * b[j];
        }
    }

    if (mode < 3) {
        float* dst = (mode == 0) ? g_Q : ((mode == 1) ? g_K : g_V);
        #pragma unroll
        for (int i = 0; i < 8; i++) {
            int m = m0 + ty*8 + i;
            int b  = m >> 11;          // /2048
            int n  = m & 2047;
            #pragma unroll
            for (int j = 0; j < 8; j++) {
                int c = n0 + tx*8 + j;
                int h = c / HD, d = c % HD;
                dst[((size_t)(b*HEADS + h)*NTOK + n)*HD + d] = acc[i][j] + bias[c];
            }
        }
    } else {
        #pragma unroll
        for (int i = 0; i < 8; i++) {
            size_t m = m0 + ty*8 + i;
            #pragma unroll
            for (int j = 0; j < 8; j++) {
                int c = n0 + tx*8 + j;
                size_t idx = m*CDIM + c;
                outp[idx] = acc[i][j] + bias[c] + g_Y[idx] + addsrc[idx];
            }
        }
    }
}

// ---------------------------------------------------------------------------
// Flash attention (fp32): one block = 64 query rows of one (b,h).
// 256 threads. Online softmax. Writes y = attn_out + x into g_Y ([B,N,C]).
// dyn smem: Qst[48][64] | Kst[48][64] | Vs[64][48] | Ss[64][68]
// ---------------------------------------------------------------------------
#define ATTN_SMEM ((3*48*64 + 64*68) * 4)

__global__ __launch_bounds__(256) void attn_kernel(const float* __restrict__ x)
{
    extern __shared__ float sm[];
    float* Qst = sm;                  // [48][64] transposed
    float* Kst = sm + 48*64;          // [48][64] transposed
    float* Vs  = sm + 2*48*64;        // [64][48]
    float* Ss  = sm + 3*48*64;        // [64][68]

    int tid = threadIdx.x;
    int bh  = blockIdx.y;
    int q0  = blockIdx.x * 64;

    const float* Qg = g_Q + (size_t)bh * NTOK * HD;
    const float* Kg = g_K + (size_t)bh * NTOK * HD;
    const float* Vg = g_V + (size_t)bh * NTOK * HD;

    // load Q tile, transposed
    for (int t = tid; t < 64*12; t += 256) {
        int r = t / 12, c4 = (t % 12) * 4;
        float4 v = *(const float4*)(Qg + (size_t)(q0 + r)*HD + c4);
        Qst[(c4+0)*64 + r] = v.x;
        Qst[(c4+1)*64 + r] = v.y;
        Qst[(c4+2)*64 + r] = v.z;
        Qst[(c4+3)*64 + r] = v.w;
    }

    int ty = tid >> 4, tx = tid & 15;   // S-compute mapping (4x4 per thread)
    int r = tid >> 2, lane4 = tid & 3;  // softmax/PV mapping (4 threads/row)

    float m_run = -1e30f, l_run = 0.f;
    float o[12];
    #pragma unroll
    for (int i = 0; i < 12; i++) o[i] = 0.f;

    for (int kt = 0; kt < NTOK/64; kt++) {
        __syncthreads();   // previous iter fully consumed K/V/S
        int k0 = kt * 64;
        for (int t = tid; t < 64*12; t += 256) {
            int rr = t / 12, c4 = (t % 12) * 4;
            float4 kv = *(const float4*)(Kg + (size_t)(k0+rr)*HD + c4);
            Kst[(c4+0)*64 + rr] = kv.x;
            Kst[(c4+1)*64 + rr] = kv.y;
            Kst[(c4+2)*64 + rr] = kv.z;
            Kst[(c4+3)*64 + rr] = kv.w;
            float4 vv = *(const float4*)(Vg + (size_t)(k0+rr)*HD + c4);
            *(float4*)(Vs + rr*48 + c4) = vv;
        }
        __syncthreads();

        // S = (Q K^T) * SCALE
        float acc[4][4];
        #pragma unroll
        for (int i = 0; i < 4; i++)
            #pragma unroll
            for (int j = 0; j < 4; j++) acc[i][j] = 0.f;

        #pragma unroll
        for (int kk = 0; kk < HD; kk++) {
            float4 a = *(const float4*)(Qst + kk*64 + ty*4);
            float4 b = *(const float4*)(Kst + kk*64 + tx*4);
            acc[0][0] += a.x*b.x; acc[0][1] += a.x*b.y; acc[0][2] += a.x*b.z; acc[0][3] += a.x*b.w;
            acc[1][0] += a.y*b.x; acc[1][1] += a.y*b.y; acc[1][2] += a.y*b.z; acc[1][3] += a.y*b.w;
            acc[2][0] += a.z*b.x; acc[2][1] += a.z*b.y; acc[2][2] += a.z*b.z; acc[2][3] += a.z*b.w;
            acc[3][0] += a.w*b.x; acc[3][1] += a.w*b.y; acc[3][2] += a.w*b.z; acc[3][3] += a.w*b.w;
        }
        #pragma unroll
        for (int i = 0; i < 4; i++) {
            float4 s;
            s.x = acc[i][0]*SCALE; s.y = acc[i][1]*SCALE;
            s.z = acc[i][2]*SCALE; s.w = acc[i][3]*SCALE;
            *(float4*)(Ss + (ty*4+i)*68 + tx*4) = s;
        }
        __syncthreads();

        // online softmax on row r (4 threads per row)
        float mt = -1e30f;
        #pragma unroll
        for (int jj = 0; jj < 16; jj++)
            mt = fmaxf(mt, Ss[r*68 + lane4*16 + jj]);
        mt = fmaxf(mt, __shfl_xor_sync(0xffffffffu, mt, 1));
        mt = fmaxf(mt, __shfl_xor_sync(0xffffffffu, mt, 2));
        float m_new = fmaxf(m_run, mt);
        float corr = __expf(m_run - m_new);
        float ls = 0.f;
        #pragma unroll
        for (int jj = 0; jj < 16; jj++) {
            float p = __expf(Ss[r*68 + lane4*16 + jj] - m_new);
            Ss[r*68 + lane4*16 + jj] = p;
            ls += p;
        }
        ls += __shfl_xor_sync(0xffffffffu, ls, 1);
        ls += __shfl_xor_sync(0xffffffffu, ls, 2);
        l_run = l_run * corr + ls;
        m_run = m_new;
        #pragma unroll
        for (int i = 0; i < 12; i++) o[i] *= corr;
        __syncwarp();   // P writes visible across the 4-lane group

        // O += P @ V  (each thread: 12 d-values of row r)
        #pragma unroll 4
        for (int j = 0; j < 64; j++) {
            float p = Ss[r*68 + j];
            const float* vrow = Vs + j*48 + lane4*12;
            float4 v0 = *(const float4*)(vrow);
            float4 v1 = *(const float4*)(vrow + 4);
            float4 v2 = *(const float4*)(vrow + 8);
            o[0] += p*v0.x; o[1]  += p*v0.y; o[2]  += p*v0.z; o[3]  += p*v0.w;
            o[4] += p*v1.x; o[5]  += p*v1.y; o[6]  += p*v1.z; o[7]  += p*v1.w;
            o[8] += p*v2.x; o[9]  += p*v2.y; o[10] += p*v2.z; o[11] += p*v2.w;
        }
    }

    float inv = 1.f / l_run;
    int b = bh >> 4, h = bh & 15;
    int n = q0 + r;
    size_t idx = ((size_t)b*NTOK + n)*CDIM + h*HD + lane4*12;
    #pragma unroll
    for (int i = 0; i < 12; i++)
        g_Y[idx + i] = o[i]*inv + x[idx + i];
}

// ---------------------------------------------------------------------------
extern "C" void kernel_launch(void* const* d_in, const int* in_sizes, int n_in,
                              void* d_out, int out_size)
{
    const float* x  = (const float*)d_in[0];
    const float* wq = (const float*)d_in[1];
    const float* bq = (const float*)d_in[2];
    const float* wk = (const float*)d_in[3];
    const float* bk = (const float*)d_in[4];
    const float* wv = (const float*)d_in[5];
    const float* bv = (const float*)d_in[6];
    const float* wo = (const float*)d_in[7];
    const float* bo = (const float*)d_in[8];
    float* out = (float*)d_out;

    dim3 ggrid(CDIM/128, MROWS/128);   // (6, 64)
    gemm_kernel<<<ggrid, 256>>>(x, wq, bq, out, x, 0);
    gemm_kernel<<<ggrid, 256>>>(x, wk, bk, out, x, 1);
    gemm_kernel<<<ggrid, 256>>>(x, wv, bv, out, x, 2);

    cudaFuncSetAttribute(attn_kernel,
                         cudaFuncAttributeMaxDynamicSharedMemorySize, ATTN_SMEM);
    attn_kernel<<<dim3(NTOK/64, BATCH*HEADS), 256, ATTN_SMEM>>>(x);

    gemm_kernel<<<ggrid, 256>>>(nullptr, wo, bo, out, x, 3);
}

// round 3
// speedup vs baseline: 8.1307x; 8.1307x over previous
#include <cuda_runtime.h>
#include <cuda_fp16.h>
#include <cstdint>
#include <math.h>

#define BATCH   4
#define NTOK    2048
#define CDIM    768
#define HEADS   16
#define HD      48
#define MROWS   (BATCH*NTOK)          // 8192
#define SCALE   0.14433756729740643f  // 48^-0.5

// ---------------- scratch (device globals; no allocation allowed) ----------
__device__ __align__(256) __half g_Xh[(size_t)MROWS*CDIM];
__device__ __align__(256) __half g_Wh[4][(size_t)CDIM*CDIM];   // q,k,v,o
__device__ __align__(256) __half g_Qh[(size_t)MROWS*CDIM];     // [B,H,N,D], Q pre-scaled
__device__ __align__(256) __half g_Kh[(size_t)MROWS*CDIM];
__device__ __align__(256) __half g_Vh[(size_t)MROWS*CDIM];
__device__ __align__(256) float  g_Y [(size_t)MROWS*CDIM];     // y = attn_out + x (fp32)
__device__ __align__(256) __half g_Yh[(size_t)MROWS*CDIM];     // fp16 copy of y

// ---------------------------------------------------------------------------
__device__ __forceinline__ unsigned cvta_s(const void* p) {
    return (unsigned)__cvta_generic_to_shared(p);
}
__device__ __forceinline__ void ldsm_x4(unsigned& r0, unsigned& r1,
                                        unsigned& r2, unsigned& r3, unsigned a) {
    asm volatile("ldmatrix.sync.aligned.m8n8.x4.shared.b16 {%0,%1,%2,%3},[%4];"
                 : "=r"(r0), "=r"(r1), "=r"(r2), "=r"(r3) : "r"(a));
}
__device__ __forceinline__ void ldsm_x4_t(unsigned& r0, unsigned& r1,
                                          unsigned& r2, unsigned& r3, unsigned a) {
    asm volatile("ldmatrix.sync.aligned.m8n8.x4.trans.shared.b16 {%0,%1,%2,%3},[%4];"
                 : "=r"(r0), "=r"(r1), "=r"(r2), "=r"(r3) : "r"(a));
}
__device__ __forceinline__ void mma16816(float* c, unsigned a0, unsigned a1,
                                         unsigned a2, unsigned a3,
                                         unsigned b0, unsigned b1) {
    asm volatile("mma.sync.aligned.m16n8k16.row.col.f32.f16.f16.f32 "
                 "{%0,%1,%2,%3},{%4,%5,%6,%7},{%8,%9},{%0,%1,%2,%3};"
                 : "+f"(c[0]), "+f"(c[1]), "+f"(c[2]), "+f"(c[3])
                 : "r"(a0), "r"(a1), "r"(a2), "r"(a3), "r"(b0), "r"(b1));
}
__device__ __forceinline__ unsigned f2_to_h2(float a, float b) {
    __half2 h = __floats2half2_rn(a, b);
    unsigned u;
    u = *reinterpret_cast<unsigned*>(&h);
    return u;
}

// ---------------------------------------------------------------------------
// fp32 -> fp16 conversion. which: 0=x->g_Xh, 1..4 = w -> g_Wh[which-1]
// ---------------------------------------------------------------------------
__global__ void cvt_kernel(const float* __restrict__ src, int which, int n4)
{
    int i = blockIdx.x * 256 + threadIdx.x;
    if (i >= n4) return;
    __half2* dst = (which == 0) ? (__half2*)g_Xh : (__half2*)g_Wh[which - 1];
    float4 v = ((const float4*)src)[i];
    dst[2*i]   = __floats2half2_rn(v.x, v.y);
    dst[2*i+1] = __floats2half2_rn(v.z, v.w);
}

// ---------------------------------------------------------------------------
// HGEMM: C[m][c] = sum_k A[m][k]*W[c][k], fp16 in / fp32 acc.
// 128x128 block, BK=32, 256 threads (8 warps, 2x4), warp tile 64x32.
// mode 0/1/2: A=g_Xh, W=g_Wh[mode]; epilogue scatter (acc+bias)(*SCALE for Q)
//             -> g_Qh/g_Kh/g_Vh in [B,H,N,D] fp16.
// mode 3:     A=g_Yh, W=g_Wh[3];  out = acc + bias + g_Y + x.
// ---------------------------------------------------------------------------
__global__ __launch_bounds__(256) void hgemm_kernel(
    const float* __restrict__ bias, float* __restrict__ outp,
    const float* __restrict__ x, int mode)
{
    __shared__ __half As[128 * 40];
    __shared__ __half Bs[128 * 40];

    const __half* A = (mode == 3) ? g_Yh : g_Xh;
    const __half* W = g_Wh[(mode == 3) ? 3 : mode];

    int tid = threadIdx.x, lane = tid & 31, warp = tid >> 5;
    int m0 = blockIdx.y * 128, n0 = blockIdx.x * 128;
    int wm = (warp >> 2) * 64, wn = (warp & 3) * 32;

    int lr = tid >> 2;       // 0..63
    int lc = tid & 3;        // 16B chunk (8 halfs)

    float acc[4][4][4];
    #pragma unroll
    for (int i = 0; i < 4; i++)
        #pragma unroll
        for (int j = 0; j < 4; j++)
            #pragma unroll
            for (int e = 0; e < 4; e++) acc[i][j][e] = 0.f;

    uint4 pa[2], pb[2];
    #pragma unroll
    for (int i = 0; i < 2; i++) {
        pa[i] = *(const uint4*)(A + (size_t)(m0 + lr + i*64) * CDIM + lc*8);
        pb[i] = *(const uint4*)(W + (size_t)(n0 + lr + i*64) * CDIM + lc*8);
    }

    for (int kt = 0; kt < CDIM/32; kt++) {
        __syncthreads();
        #pragma unroll
        for (int i = 0; i < 2; i++) {
            *(uint4*)&As[(lr + i*64)*40 + lc*8] = pa[i];
            *(uint4*)&Bs[(lr + i*64)*40 + lc*8] = pb[i];
        }
        __syncthreads();
        if (kt < CDIM/32 - 1) {
            int k8 = (kt + 1) * 32 + lc*8;
            #pragma unroll
            for (int i = 0; i < 2; i++) {
                pa[i] = *(const uint4*)(A + (size_t)(m0 + lr + i*64)*CDIM + k8);
                pb[i] = *(const uint4*)(W + (size_t)(n0 + lr + i*64)*CDIM + k8);
            }
        }
        #pragma unroll
        for (int s = 0; s < 2; s++) {
            int k = s * 16;
            unsigned af[4][4];
            #pragma unroll
            for (int mt = 0; mt < 4; mt++) {
                unsigned addr = cvta_s(&As[(wm + mt*16 + (lane & 15))*40
                                           + k + ((lane >> 4) << 3)]);
                ldsm_x4(af[mt][0], af[mt][1], af[mt][2], af[mt][3], addr);
            }
            unsigned bf[4][2];
            int g = lane >> 3, L = lane & 7;
            #pragma unroll
            for (int nt2 = 0; nt2 < 2; nt2++) {
                int brow = wn + nt2*16 + ((g >> 1) << 3) + L;
                int bcol = k + ((g & 1) << 3);
                unsigned r0, r1, r2, r3;
                ldsm_x4(r0, r1, r2, r3, cvta_s(&Bs[brow*40 + bcol]));
                bf[nt2*2][0] = r0;   bf[nt2*2][1] = r1;
                bf[nt2*2+1][0] = r2; bf[nt2*2+1][1] = r3;
            }
            #pragma unroll
            for (int mt = 0; mt < 4; mt++)
                #pragma unroll
                for (int nt = 0; nt < 4; nt++)
                    mma16816(acc[mt][nt], af[mt][0], af[mt][1], af[mt][2],
                             af[mt][3], bf[nt][0], bf[nt][1]);
        }
    }

    // epilogue
    if (mode < 3) {
        __half* dst = (mode == 0) ? g_Qh : ((mode == 1) ? g_Kh : g_Vh);
        float sc = (mode == 0) ? SCALE : 1.f;
        #pragma unroll
        for (int mt = 0; mt < 4; mt++) {
            #pragma unroll
            for (int nt = 0; nt < 4; nt++) {
                int mr = m0 + wm + mt*16 + (lane >> 2);
                int c  = n0 + wn + nt*8 + ((lane & 3) << 1);
                int hh = c / HD, d = c - hh*HD;
                int bb = mr >> 11, nn = mr & 2047;
                size_t base = (size_t)(bb*HEADS + hh) * NTOK * HD + d;
                __half2 v0 = __floats2half2_rn((acc[mt][nt][0] + bias[c])*sc,
                                               (acc[mt][nt][1] + bias[c+1])*sc);
                __half2 v1 = __floats2half2_rn((acc[mt][nt][2] + bias[c])*sc,
                                               (acc[mt][nt][3] + bias[c+1])*sc);
                *(__half2*)&dst[base + (size_t)nn*HD]     = v0;
                *(__half2*)&dst[base + (size_t)(nn+8)*HD] = v1;
            }
        }
    } else {
        #pragma unroll
        for (int mt = 0; mt < 4; mt++) {
            #pragma unroll
            for (int nt = 0; nt < 4; nt++) {
                int mr = m0 + wm + mt*16 + (lane >> 2);
                int c  = n0 + wn + nt*8 + ((lane & 3) << 1);
                size_t i0 = (size_t)mr * CDIM + c;
                size_t i1 = (size_t)(mr + 8) * CDIM + c;
                outp[i0]   = acc[mt][nt][0] + bias[c]   + g_Y[i0]   + x[i0];
                outp[i0+1] = acc[mt][nt][1] + bias[c+1] + g_Y[i0+1] + x[i0+1];
                outp[i1]   = acc[mt][nt][2] + bias[c]   + g_Y[i1]   + x[i1];
                outp[i1+1] = acc[mt][nt][3] + bias[c+1] + g_Y[i1+1] + x[i1+1];
            }
        }
    }
}

// ---------------------------------------------------------------------------
// FlashAttention-2 fp16: block = 64 q-rows of one (b,h), 4 warps x 16 rows.
// Q pre-scaled by SCALE. Writes y = softmax(QK^T)V + x to g_Y (f32), g_Yh (f16).
// ---------------------------------------------------------------------------
__global__ __launch_bounds__(128) void fattn_kernel(const float* __restrict__ x)
{
    __shared__ __half Qs[64*56];
    __shared__ __half Ks[64*56];
    __shared__ __half Vs[64*56];

    int tid = threadIdx.x, lane = tid & 31, w = tid >> 5;
    int bh = blockIdx.y, q0 = blockIdx.x * 64;
    int b = bh >> 4, hh = bh & 15;

    const __half* Qg = g_Qh + (size_t)bh * NTOK * HD;
    const __half* Kg = g_Kh + (size_t)bh * NTOK * HD;
    const __half* Vg = g_Vh + (size_t)bh * NTOK * HD;

    // load Q tile (64 x 48 halfs, 6 x uint4 per row)
    #pragma unroll
    for (int i = 0; i < 3; i++) {
        int idx = tid + i*128;
        int r = idx / 6, c = idx % 6;
        *(uint4*)&Qs[r*56 + c*8] =
            *(const uint4*)(Qg + (size_t)(q0 + r)*HD + c*8);
    }
    __syncthreads();

    unsigned qa[3][4];
    #pragma unroll
    for (int ks = 0; ks < 3; ks++)
        ldsm_x4(qa[ks][0], qa[ks][1], qa[ks][2], qa[ks][3],
                cvta_s(&Qs[(w*16 + (lane & 15))*56 + ks*16 + ((lane >> 4) << 3)]));

    float m_run[2] = {-1e30f, -1e30f}, l_run[2] = {0.f, 0.f};
    float oacc[6][4];
    #pragma unroll
    for (int i = 0; i < 6; i++)
        #pragma unroll
        for (int e = 0; e < 4; e++) oacc[i][e] = 0.f;

    int g = lane >> 3, L = lane & 7;

    for (int kt = 0; kt < NTOK/64; kt++) {
        __syncthreads();
        int k0 = kt * 64;
        #pragma unroll
        for (int i = 0; i < 3; i++) {
            int idx = tid + i*128;
            int r = idx / 6, c = idx % 6;
            *(uint4*)&Ks[r*56 + c*8] = *(const uint4*)(Kg + (size_t)(k0+r)*HD + c*8);
            *(uint4*)&Vs[r*56 + c*8] = *(const uint4*)(Vg + (size_t)(k0+r)*HD + c*8);
        }
        __syncthreads();

        // S = Q K^T  (already scaled via Q)
        float sacc[8][4];
        #pragma unroll
        for (int i = 0; i < 8; i++)
            #pragma unroll
            for (int e = 0; e < 4; e++) sacc[i][e] = 0.f;

        #pragma unroll
        for (int ks = 0; ks < 3; ks++) {
            #pragma unroll
            for (int nt2 = 0; nt2 < 4; nt2++) {
                int brow = nt2*16 + ((g >> 1) << 3) + L;
                int bcol = ks*16 + ((g & 1) << 3);
                unsigned r0, r1, r2, r3;
                ldsm_x4(r0, r1, r2, r3, cvta_s(&Ks[brow*56 + bcol]));
                mma16816(sacc[nt2*2],   qa[ks][0], qa[ks][1], qa[ks][2], qa[ks][3], r0, r1);
                mma16816(sacc[nt2*2+1], qa[ks][0], qa[ks][1], qa[ks][2], qa[ks][3], r2, r3);
            }
        }

        // online softmax (rows lane>>2 and +8 of this warp's 16)
        float mt0 = -1e30f, mt1 = -1e30f;
        #pragma unroll
        for (int nt = 0; nt < 8; nt++) {
            mt0 = fmaxf(mt0, fmaxf(sacc[nt][0], sacc[nt][1]));
            mt1 = fmaxf(mt1, fmaxf(sacc[nt][2], sacc[nt][3]));
        }
        mt0 = fmaxf(mt0, __shfl_xor_sync(0xffffffffu, mt0, 1));
        mt0 = fmaxf(mt0, __shfl_xor_sync(0xffffffffu, mt0, 2));
        mt1 = fmaxf(mt1, __shfl_xor_sync(0xffffffffu, mt1, 1));
        mt1 = fmaxf(mt1, __shfl_xor_sync(0xffffffffu, mt1, 2));

        float mn0 = fmaxf(m_run[0], mt0), mn1 = fmaxf(m_run[1], mt1);
        float cr0 = __expf(m_run[0] - mn0), cr1 = __expf(m_run[1] - mn1);
        m_run[0] = mn0; m_run[1] = mn1;

        float ls0 = 0.f, ls1 = 0.f;
        #pragma unroll
        for (int nt = 0; nt < 8; nt++) {
            float p0 = __expf(sacc[nt][0] - mn0);
            float p1 = __expf(sacc[nt][1] - mn0);
            float p2 = __expf(sacc[nt][2] - mn1);
            float p3 = __expf(sacc[nt][3] - mn1);
            sacc[nt][0] = p0; sacc[nt][1] = p1; sacc[nt][2] = p2; sacc[nt][3] = p3;
            ls0 += p0 + p1; ls1 += p2 + p3;
        }
        ls0 += __shfl_xor_sync(0xffffffffu, ls0, 1);
        ls0 += __shfl_xor_sync(0xffffffffu, ls0, 2);
        ls1 += __shfl_xor_sync(0xffffffffu, ls1, 1);
        ls1 += __shfl_xor_sync(0xffffffffu, ls1, 2);
        l_run[0] = l_run[0]*cr0 + ls0;
        l_run[1] = l_run[1]*cr1 + ls1;

        #pragma unroll
        for (int nt = 0; nt < 6; nt++) {
            oacc[nt][0] *= cr0; oacc[nt][1] *= cr0;
            oacc[nt][2] *= cr1; oacc[nt][3] *= cr1;
        }

        // O += P V  (P in regs -> a-frags; V via ldmatrix.trans)
        #pragma unroll
        for (int j2 = 0; j2 < 4; j2++) {
            unsigned a0 = f2_to_h2(sacc[2*j2][0],   sacc[2*j2][1]);
            unsigned a1 = f2_to_h2(sacc[2*j2][2],   sacc[2*j2][3]);
            unsigned a2 = f2_to_h2(sacc[2*j2+1][0], sacc[2*j2+1][1]);
            unsigned a3 = f2_to_h2(sacc[2*j2+1][2], sacc[2*j2+1][3]);
            #pragma unroll
            for (int nt2 = 0; nt2 < 3; nt2++) {
                int vrow = j2*16 + ((g & 1) << 3) + L;
                int vcol = nt2*16 + ((g >> 1) << 3);
                unsigned r0, r1, r2, r3;
                ldsm_x4_t(r0, r1, r2, r3, cvta_s(&Vs[vrow*56 + vcol]));
                mma16816(oacc[nt2*2],   a0, a1, a2, a3, r0, r1);
                mma16816(oacc[nt2*2+1], a0, a1, a2, a3, r2, r3);
            }
        }
    }

    // epilogue: y = o/l + x
    float inv0 = 1.f / l_run[0], inv1 = 1.f / l_run[1];
    int n_0 = q0 + w*16 + (lane >> 2);
    int n_1 = n_0 + 8;
    #pragma unroll
    for (int nt = 0; nt < 6; nt++) {
        int d = nt*8 + ((lane & 3) << 1);
        size_t i0 = ((size_t)(b*NTOK + n_0))*CDIM + hh*HD + d;
        size_t i1 = ((size_t)(b*NTOK + n_1))*CDIM + hh*HD + d;
        float y00 = oacc[nt][0]*inv0 + x[i0];
        float y01 = oacc[nt][1]*inv0 + x[i0+1];
        float y10 = oacc[nt][2]*inv1 + x[i1];
        float y11 = oacc[nt][3]*inv1 + x[i1+1];
        *(float2*)&g_Y[i0] = make_float2(y00, y01);
        *(float2*)&g_Y[i1] = make_float2(y10, y11);
        *(__half2*)&g_Yh[i0] = __floats2half2_rn(y00, y01);
        *(__half2*)&g_Yh[i1] = __floats2half2_rn(y10, y11);
    }
}

// ---------------------------------------------------------------------------
extern "C" void kernel_launch(void* const* d_in, const int* in_sizes, int n_in,
                              void* d_out, int out_size)
{
    const float* x  = (const float*)d_in[0];
    const float* wq = (const float*)d_in[1];
    const float* bq = (const float*)d_in[2];
    const float* wk = (const float*)d_in[3];
    const float* bk = (const float*)d_in[4];
    const float* wv = (const float*)d_in[5];
    const float* bv = (const float*)d_in[6];
    const float* wo = (const float*)d_in[7];
    const float* bo = (const float*)d_in[8];
    float* out = (float*)d_out;

    int n4x = MROWS*CDIM/4;
    int n4w = CDIM*CDIM/4;
    cvt_kernel<<<(n4x + 255)/256, 256>>>(x,  0, n4x);
    cvt_kernel<<<(n4w + 255)/256, 256>>>(wq, 1, n4w);
    cvt_kernel<<<(n4w + 255)/256, 256>>>(wk, 2, n4w);
    cvt_kernel<<<(n4w + 255)/256, 256>>>(wv, 3, n4w);
    cvt_kernel<<<(n4w + 255)/256, 256>>>(wo, 4, n4w);

    dim3 gg(CDIM/128, MROWS/128);   // (6, 64)
    hgemm_kernel<<<gg, 256>>>(bq, out, x, 0);
    hgemm_kernel<<<gg, 256>>>(bk, out, x, 1);
    hgemm_kernel<<<gg, 256>>>(bv, out, x, 2);

    fattn_kernel<<<dim3(NTOK/64, BATCH*HEADS), 128>>>(x);

    hgemm_kernel<<<gg, 256>>>(bo, out, x, 3);
}